// round 11
// baseline (speedup 1.0000x reference)
#include <cuda_runtime.h>

#define B_   16
#define T_   256
#define NTR_ 1024
#define NTE_ 256
#define NALL 1280
#define NG   16           // n's per block

#define L2E      1.4426950408889634f
#define LOG2_L2E 0.5287663729448977f

typedef unsigned long long u64;

__device__ __forceinline__ float ex2(float x) {
    float r; asm("ex2.approx.f32 %0, %1;" : "=f"(r) : "f"(x)); return r;
}
__device__ __forceinline__ u64 pk(float lo, float hi) {
    u64 r; asm("mov.b64 %0, {%1,%2};" : "=l"(r) : "f"(lo), "f"(hi)); return r;
}
__device__ __forceinline__ void upk(u64 v, float& lo, float& hi) {
    asm("mov.b64 {%0,%1}, %2;" : "=f"(lo), "=f"(hi) : "l"(v));
}
__device__ __forceinline__ u64 f2fma(u64 a, u64 b, u64 c) {
    u64 d; asm("fma.rn.f32x2 %0, %1, %2, %3;" : "=l"(d) : "l"(a), "l"(b), "l"(c)); return d;
}
__device__ __forceinline__ u64 f2mul(u64 a, u64 b) {
    u64 d; asm("mul.rn.f32x2 %0, %1, %2;" : "=l"(d) : "l"(a), "l"(b)); return d;
}
__device__ __forceinline__ u64 f2add(u64 a, u64 b) {
    u64 d; asm("add.rn.f32x2 %0, %1, %2;" : "=l"(d) : "l"(a), "l"(b)); return d;
}
// Volatile 128-bit shared load: stays in-loop so values never occupy
// long-lived registers.
__device__ __forceinline__ void ldsV(unsigned addr, u64& a, u64& b) {
    asm volatile("ld.shared.v2.u64 {%0,%1}, [%2];" : "=l"(a), "=l"(b) : "r"(addr));
}

// Block = (b, group of NG n's). 64 threads; thread tq owns the adjacent
// t-quad (4tq..4tq+3) as TWO packed f32x2 pairs, loops over 16 n's.
// Per-thread lap inputs (zx/zy/Lt pairs) live in field-major smem and are
// re-fetched in-loop (register relief -> 14 blocks/SM).
__global__ void __launch_bounds__(64, 14)
decoder_fused(const float* __restrict__ z0,
              const float* __restrict__ z1,
              const float* __restrict__ coeff0,
              const float* __restrict__ mean0,
              const float* __restrict__ log_var0,
              const float* __restrict__ coeff1,
              const float* __restrict__ mean1,
              const float* __restrict__ log_var1,
              const float* __restrict__ rf_tr0,
              const float* __restrict__ rf_tr1,
              const float* __restrict__ rf_te0,
              const float* __restrict__ rf_te1,
              const float* __restrict__ ew_tr,
              const float* __restrict__ ew_te,
              const float* __restrict__ lfs_tr,
              const float* __restrict__ lfs_te,
              float* __restrict__ out)
{
    __shared__ float4     sN[NG][5];   // per-n consts, duplicated pairs
    __shared__ u64        sC[16];      // bicubic coeffs, duplicated pairs
    __shared__ ulonglong2 sZ[3][64];   // per-thread (zx, zy, Lt) pair-pairs

    const int tid = threadIdx.x;
    const int bid = blockIdx.x;
    const int b   = bid / (NALL / NG);
    const int ng  = bid % (NALL / NG);
    const int n0  = ng * NG;

    // Global scalars every thread needs (broadcast loads, fast-math).
    const float dx  = mean1[8] - mean1[0];
    const float dy  = mean1[3] - mean1[1];
    const float ivx = __expf(-2.0f * log_var1[0]);  // 1/vx^2
    const float ivy = __expf(-2.0f * log_var1[1]);
    const float axl = ivx * L2E, ayl = ivy * L2E;
    const float kxl = 2.0f * dx * axl, kyl = 2.0f * dy * ayl;

    // ---- in-block per-n constant prep (fast-math intrinsics only) ----
    if (tid < NG) {
        int n = n0 + tid;
        int nn; const float *rf0, *rf1, *ew, *lfs;
        if (n < NTR_) { nn = n;        rf0 = rf_tr0; rf1 = rf_tr1; ew = ew_tr; lfs = lfs_tr; }
        else          { nn = n - NTR_; rf0 = rf_te0; rf1 = rf_te1; ew = ew_te; lfs = lfs_te; }

        // Torus: w0*e0 ~= EW0 + v*(EW0 + EJ*v), v = pA*s + qA*c (= A*w, |w|<=0.04)
        float mu  = mean0[0];
        float smu, cmu, sr, cr;
        __sincosf(mu, &smu, &cmu);
        __sincosf(rf0[nn], &sr, &cr);
        float ms  = smu - sr;
        float mc  = cmu - cr;
        float iv0 = __expf(-2.0f * log_var0[0]);
        float A   = coeff0[0] * __expf(-(1.0f + ms * ms + mc * mc) * iv0);
        float pA  = 2.0f * ms * iv0 * A;
        float qA  = 2.0f * mc * iv0 * A;

        float e0w = ew[nn * 2], e1w = ew[nn * 2 + 1];
        float mx  = fmaxf(e0w, e1w);
        float ea  = __expf(e0w - mx), eb = __expf(e1w - mx);
        float scl = __expf(lfs[nn]) / (ea + eb);
        float EW0 = ea * scl * __expf(A);               // w0 * exp(A)
        float EJ  = EW0 * (1.0f + A) / (2.0f * A);      // EW0 * J
        float W1  = eb * scl;

        float rx  = rf1[nn * 2 + 0] - mean1[0];
        float ry  = rf1[nn * 2 + 1] - mean1[1];
        float Rx  = ex2(kxl * rx), Ry = ex2(kyl * ry);
        float Px  = -2.0f * axl * rx, Py = -2.0f * ayl * ry;
        float Ln  = -axl * rx * rx - ayl * ry * ry;

        sN[tid][0] = make_float4(pA, pA, qA,  qA);
        sN[tid][1] = make_float4(EJ, EJ, EW0, EW0);
        sN[tid][2] = make_float4(Rx, Rx, Ry,  Ry);
        sN[tid][3] = make_float4(Px, Px, Py,  Py);
        sN[tid][4] = make_float4(Ln, Ln, W1,  W1);
    } else if (tid >= 32 && tid < 48) {
        int e = tid - 32;
        int i = e & 3, j = e >> 2;
        float v = coeff1[i * 4 + j] *
                  __expf(-(float)(i * i) * dx * dx * ivx - (float)(j * j) * dy * dy * ivy);
        sC[e] = pk(v, v);
    }

    // ---- per-thread t-quad prologue: two packed pairs ----
    const int tq = tid;
    float4 za = ((const float4*)z0)[b * (T_ / 4) + tq];          // z0[4tq..4tq+3]
    float4 q0 = ((const float4*)z1)[b * (T_ / 2) + 2 * tq];      // (zx0,zy0,zx1,zy1)
    float4 q1 = ((const float4*)z1)[b * (T_ / 2) + 2 * tq + 1];  // (zx2,zy2,zx3,zy3)

    float s0, c0, s1, c1, s2, c2, s3, c3;
    __sincosf(za.x, &s0, &c0);
    __sincosf(za.y, &s1, &c1);
    __sincosf(za.z, &s2, &c2);
    __sincosf(za.w, &s3, &c3);

    u64 ssp0 = pk(s0, s1), ccp0 = pk(c0, c1);
    u64 ssp1 = pk(s2, s3), ccp1 = pk(c2, c3);
    u64 Txp0 = pk(ex2(kxl * q0.x), ex2(kxl * q0.z));
    u64 Typ0 = pk(ex2(kyl * q0.y), ex2(kyl * q0.w));
    u64 Txp1 = pk(ex2(kxl * q1.x), ex2(kxl * q1.z));
    u64 Typ1 = pk(ex2(kyl * q1.y), ex2(kyl * q1.w));

    // lap inputs -> field-major smem (own slot; same-thread readback)
    sZ[0][tid] = make_ulonglong2(pk(q0.x, q0.z), pk(q1.x, q1.z));   // zx pairs
    sZ[1][tid] = make_ulonglong2(pk(q0.y, q0.w), pk(q1.y, q1.w));   // zy pairs
    sZ[2][tid] = make_ulonglong2(
        pk(fmaf(-axl * q0.x, q0.x, fmaf(-ayl * q0.y, q0.y, LOG2_L2E)),
           fmaf(-axl * q0.z, q0.z, fmaf(-ayl * q0.w, q0.w, LOG2_L2E))),
        pk(fmaf(-axl * q1.x, q1.x, fmaf(-ayl * q1.y, q1.y, LOG2_L2E)),
           fmaf(-axl * q1.z, q1.z, fmaf(-ayl * q1.w, q1.w, LOG2_L2E))));

    __syncthreads();

    float* op;
    if (n0 < NTR_) op = out + (b * NTR_ + n0) * T_ + 4 * tq;
    else           op = out + B_ * NTR_ * T_ + (b * NTE_ + (n0 - NTR_)) * T_ + 4 * tq;

    unsigned cbase = (unsigned)__cvta_generic_to_shared(sC);
    unsigned zxad  = (unsigned)__cvta_generic_to_shared(&sZ[0][tid]);
    unsigned zyad  = (unsigned)__cvta_generic_to_shared(&sZ[1][tid]);
    unsigned ltad  = (unsigned)__cvta_generic_to_shared(&sZ[2][tid]);

#pragma unroll
    for (int qi = 0; qi < NG; qi++) {
        const ulonglong2* pn = (const ulonglong2*)sN[qi];
        ulonglong2 A0 = pn[0], A1 = pn[1], A2 = pn[2], A3 = pn[3], A4 = pn[4];
        u64 pAp = A0.x, qAp = A0.y, EJp = A1.x, EW0p = A1.y;
        u64 Rxp = A2.x, Ryp = A2.y, Pxp = A3.x, Pyp = A3.y;
        u64 Lnp = A4.x, W1p = A4.y;

        float a0, a1;

        // lap inputs from smem (in-loop, register-free)
        u64 zx0, zx1, zy0, zy1, lt0, lt1;
        ldsV(zxad, zx0, zx1);
        ldsV(zyad, zy0, zy1);
        ldsV(ltad, lt0, lt1);

        // Euclidean leads (MUFU overlaps the FMA work below)
        u64 lap0 = f2fma(Pxp, zx0, f2fma(Pyp, zy0, f2add(Lnp, lt0)));
        u64 lap1 = f2fma(Pxp, zx1, f2fma(Pyp, zy1, f2add(Lnp, lt1)));
        upk(lap0, a0, a1);
        u64 lead0 = pk(ex2(a0), ex2(a1));
        upk(lap1, a0, a1);
        u64 lead1 = pk(ex2(a0), ex2(a1));

        u64 tx0 = f2mul(Rxp, Txp0), ty0 = f2mul(Ryp, Typ0);
        u64 tx1 = f2mul(Rxp, Txp1), ty1 = f2mul(Ryp, Typ1);

        // Torus (pure FMA): e0 = EW0 + v*(EW0 + EJ*v)
        u64 vv0 = f2fma(pAp, ssp0, f2mul(qAp, ccp0));
        u64 vv1 = f2fma(pAp, ssp1, f2mul(qAp, ccp1));
        u64 e0p0 = f2fma(vv0, f2fma(EJp, vv0, EW0p), EW0p);
        u64 e0p1 = f2fma(vv1, f2fma(EJp, vv1, EW0p), EW0p);

        // bicubic Horner: table loads shared across both pairs
        u64 c0r, c1r, c2r, c3r;
        ldsV(cbase +   0, c0r, c1r); ldsV(cbase +  16, c2r, c3r);
        u64 r0a = f2fma(f2fma(f2fma(c3r, tx0, c2r), tx0, c1r), tx0, c0r);
        u64 r0b = f2fma(f2fma(f2fma(c3r, tx1, c2r), tx1, c1r), tx1, c0r);
        ldsV(cbase +  32, c0r, c1r); ldsV(cbase +  48, c2r, c3r);
        u64 r1a = f2fma(f2fma(f2fma(c3r, tx0, c2r), tx0, c1r), tx0, c0r);
        u64 r1b = f2fma(f2fma(f2fma(c3r, tx1, c2r), tx1, c1r), tx1, c0r);
        ldsV(cbase +  64, c0r, c1r); ldsV(cbase +  80, c2r, c3r);
        u64 r2a = f2fma(f2fma(f2fma(c3r, tx0, c2r), tx0, c1r), tx0, c0r);
        u64 r2b = f2fma(f2fma(f2fma(c3r, tx1, c2r), tx1, c1r), tx1, c0r);
        ldsV(cbase +  96, c0r, c1r); ldsV(cbase + 112, c2r, c3r);
        u64 r3a = f2fma(f2fma(f2fma(c3r, tx0, c2r), tx0, c1r), tx0, c0r);
        u64 r3b = f2fma(f2fma(f2fma(c3r, tx1, c2r), tx1, c1r), tx1, c0r);

        u64 Sa = f2fma(f2fma(f2fma(r3a, ty0, r2a), ty0, r1a), ty0, r0a);
        u64 Sb = f2fma(f2fma(f2fma(r3b, ty1, r2b), ty1, r1b), ty1, r0b);

        // e1 = exp2(lead*S); out = e0 + W1*e1
        u64 g0 = f2mul(lead0, Sa);
        u64 g1 = f2mul(lead1, Sb);
        upk(g0, a0, a1);
        u64 e1p0 = pk(ex2(a0), ex2(a1));
        upk(g1, a0, a1);
        u64 e1p1 = pk(ex2(a0), ex2(a1));

        u64 o0 = f2fma(W1p, e1p0, e0p0);
        u64 o1 = f2fma(W1p, e1p1, e0p1);

        float4 v4;
        upk(o0, v4.x, v4.y);
        upk(o1, v4.z, v4.w);
        *reinterpret_cast<float4*>(op + qi * T_) = v4;   // STG.128, coalesced
    }
}

extern "C" void kernel_launch(void* const* d_in, const int* in_sizes, int n_in,
                              void* d_out, int out_size)
{
    const float* z0       = (const float*)d_in[0];
    const float* z1       = (const float*)d_in[1];
    const float* coeff0   = (const float*)d_in[2];
    const float* mean0    = (const float*)d_in[3];
    const float* log_var0 = (const float*)d_in[4];
    const float* coeff1   = (const float*)d_in[5];
    const float* mean1    = (const float*)d_in[6];
    const float* log_var1 = (const float*)d_in[7];
    const float* rf_tr0   = (const float*)d_in[8];
    const float* rf_tr1   = (const float*)d_in[9];
    const float* rf_te0   = (const float*)d_in[10];
    const float* rf_te1   = (const float*)d_in[11];
    const float* ew_tr    = (const float*)d_in[12];
    const float* ew_te    = (const float*)d_in[13];
    const float* lfs_tr   = (const float*)d_in[14];
    const float* lfs_te   = (const float*)d_in[15];

    decoder_fused<<<B_ * (NALL / NG), 64>>>(
        z0, z1, coeff0, mean0, log_var0, coeff1, mean1, log_var1,
        rf_tr0, rf_tr1, rf_te0, rf_te1, ew_tr, ew_te, lfs_tr, lfs_te,
        (float*)d_out);
}

// round 12
// speedup vs baseline: 1.1572x; 1.1572x over previous
#include <cuda_runtime.h>

#define B_   16
#define T_   256
#define NTR_ 1024
#define NTE_ 256
#define NALL 1280
#define NG   8            // n's per block

#define L2E      1.4426950408889634f
#define LOG2_L2E 0.5287663729448977f

typedef unsigned long long u64;

__device__ __forceinline__ float ex2(float x) {
    float r; asm("ex2.approx.f32 %0, %1;" : "=f"(r) : "f"(x)); return r;
}
__device__ __forceinline__ u64 pk(float lo, float hi) {
    u64 r; asm("mov.b64 %0, {%1,%2};" : "=l"(r) : "f"(lo), "f"(hi)); return r;
}
__device__ __forceinline__ void upk(u64 v, float& lo, float& hi) {
    asm("mov.b64 {%0,%1}, %2;" : "=f"(lo), "=f"(hi) : "l"(v));
}
__device__ __forceinline__ u64 f2fma(u64 a, u64 b, u64 c) {
    u64 d; asm("fma.rn.f32x2 %0, %1, %2, %3;" : "=l"(d) : "l"(a), "l"(b), "l"(c)); return d;
}
__device__ __forceinline__ u64 f2mul(u64 a, u64 b) {
    u64 d; asm("mul.rn.f32x2 %0, %1, %2;" : "=l"(d) : "l"(a), "l"(b)); return d;
}
__device__ __forceinline__ u64 f2add(u64 a, u64 b) {
    u64 d; asm("add.rn.f32x2 %0, %1, %2;" : "=l"(d) : "l"(a), "l"(b)); return d;
}
// Volatile 128-bit shared load: stays in-loop so values never occupy
// long-lived registers.
__device__ __forceinline__ void ldsV(unsigned addr, u64& a, u64& b) {
    asm volatile("ld.shared.v2.u64 {%0,%1}, [%2];" : "=l"(a), "=l"(b) : "r"(addr));
}

// Block = (b, group of NG n's). 64 threads; thread tq owns the adjacent
// t-quad (4tq..4tq+3) as TWO packed f32x2 pairs, loops over NG n's.
// Per-thread lap inputs (zx/zy/Lt pairs) live in field-major smem and are
// re-fetched in-loop (register relief -> 14 blocks/SM). Grid 2560 keeps the
// SMs filled to the 14-block residency cap (R11's grid-1280 mistake undone).
__global__ void __launch_bounds__(64, 14)
decoder_fused(const float* __restrict__ z0,
              const float* __restrict__ z1,
              const float* __restrict__ coeff0,
              const float* __restrict__ mean0,
              const float* __restrict__ log_var0,
              const float* __restrict__ coeff1,
              const float* __restrict__ mean1,
              const float* __restrict__ log_var1,
              const float* __restrict__ rf_tr0,
              const float* __restrict__ rf_tr1,
              const float* __restrict__ rf_te0,
              const float* __restrict__ rf_te1,
              const float* __restrict__ ew_tr,
              const float* __restrict__ ew_te,
              const float* __restrict__ lfs_tr,
              const float* __restrict__ lfs_te,
              float* __restrict__ out)
{
    __shared__ float4     sN[NG][5];   // per-n consts, duplicated pairs
    __shared__ u64        sC[16];      // bicubic coeffs, duplicated pairs
    __shared__ ulonglong2 sZ[3][64];   // per-thread (zx, zy, Lt) pair-pairs

    const int tid = threadIdx.x;
    const int bid = blockIdx.x;
    const int b   = bid / (NALL / NG);
    const int ng  = bid % (NALL / NG);
    const int n0  = ng * NG;

    // Global scalars every thread needs (broadcast loads, fast-math).
    const float dx  = mean1[8] - mean1[0];
    const float dy  = mean1[3] - mean1[1];
    const float ivx = __expf(-2.0f * log_var1[0]);  // 1/vx^2
    const float ivy = __expf(-2.0f * log_var1[1]);
    const float axl = ivx * L2E, ayl = ivy * L2E;
    const float kxl = 2.0f * dx * axl, kyl = 2.0f * dy * ayl;

    // ---- in-block per-n constant prep (fast-math intrinsics only) ----
    if (tid < NG) {
        int n = n0 + tid;
        int nn; const float *rf0, *rf1, *ew, *lfs;
        if (n < NTR_) { nn = n;        rf0 = rf_tr0; rf1 = rf_tr1; ew = ew_tr; lfs = lfs_tr; }
        else          { nn = n - NTR_; rf0 = rf_te0; rf1 = rf_te1; ew = ew_te; lfs = lfs_te; }

        // Torus: w0*e0 ~= EW0 + v*(EW0 + EJ*v), v = pA*s + qA*c (= A*w, |w|<=0.04)
        float mu  = mean0[0];
        float smu, cmu, sr, cr;
        __sincosf(mu, &smu, &cmu);
        __sincosf(rf0[nn], &sr, &cr);
        float ms  = smu - sr;
        float mc  = cmu - cr;
        float iv0 = __expf(-2.0f * log_var0[0]);
        float A   = coeff0[0] * __expf(-(1.0f + ms * ms + mc * mc) * iv0);
        float pA  = 2.0f * ms * iv0 * A;
        float qA  = 2.0f * mc * iv0 * A;

        float e0w = ew[nn * 2], e1w = ew[nn * 2 + 1];
        float mx  = fmaxf(e0w, e1w);
        float ea  = __expf(e0w - mx), eb = __expf(e1w - mx);
        float scl = __expf(lfs[nn]) / (ea + eb);
        float EW0 = ea * scl * __expf(A);               // w0 * exp(A)
        float EJ  = EW0 * (1.0f + A) / (2.0f * A);      // EW0 * J
        float W1  = eb * scl;

        float rx  = rf1[nn * 2 + 0] - mean1[0];
        float ry  = rf1[nn * 2 + 1] - mean1[1];
        float Rx  = ex2(kxl * rx), Ry = ex2(kyl * ry);
        float Px  = -2.0f * axl * rx, Py = -2.0f * ayl * ry;
        float Ln  = -axl * rx * rx - ayl * ry * ry;

        sN[tid][0] = make_float4(pA, pA, qA,  qA);
        sN[tid][1] = make_float4(EJ, EJ, EW0, EW0);
        sN[tid][2] = make_float4(Rx, Rx, Ry,  Ry);
        sN[tid][3] = make_float4(Px, Px, Py,  Py);
        sN[tid][4] = make_float4(Ln, Ln, W1,  W1);
    } else if (tid >= 32 && tid < 48) {
        int e = tid - 32;
        int i = e & 3, j = e >> 2;
        float v = coeff1[i * 4 + j] *
                  __expf(-(float)(i * i) * dx * dx * ivx - (float)(j * j) * dy * dy * ivy);
        sC[e] = pk(v, v);
    }

    // ---- per-thread t-quad prologue: two packed pairs ----
    const int tq = tid;
    float4 za = ((const float4*)z0)[b * (T_ / 4) + tq];          // z0[4tq..4tq+3]
    float4 q0 = ((const float4*)z1)[b * (T_ / 2) + 2 * tq];      // (zx0,zy0,zx1,zy1)
    float4 q1 = ((const float4*)z1)[b * (T_ / 2) + 2 * tq + 1];  // (zx2,zy2,zx3,zy3)

    float s0, c0, s1, c1, s2, c2, s3, c3;
    __sincosf(za.x, &s0, &c0);
    __sincosf(za.y, &s1, &c1);
    __sincosf(za.z, &s2, &c2);
    __sincosf(za.w, &s3, &c3);

    u64 ssp0 = pk(s0, s1), ccp0 = pk(c0, c1);
    u64 ssp1 = pk(s2, s3), ccp1 = pk(c2, c3);
    u64 Txp0 = pk(ex2(kxl * q0.x), ex2(kxl * q0.z));
    u64 Typ0 = pk(ex2(kyl * q0.y), ex2(kyl * q0.w));
    u64 Txp1 = pk(ex2(kxl * q1.x), ex2(kxl * q1.z));
    u64 Typ1 = pk(ex2(kyl * q1.y), ex2(kyl * q1.w));

    // lap inputs -> field-major smem (own slot; same-thread readback)
    sZ[0][tid] = make_ulonglong2(pk(q0.x, q0.z), pk(q1.x, q1.z));   // zx pairs
    sZ[1][tid] = make_ulonglong2(pk(q0.y, q0.w), pk(q1.y, q1.w));   // zy pairs
    sZ[2][tid] = make_ulonglong2(
        pk(fmaf(-axl * q0.x, q0.x, fmaf(-ayl * q0.y, q0.y, LOG2_L2E)),
           fmaf(-axl * q0.z, q0.z, fmaf(-ayl * q0.w, q0.w, LOG2_L2E))),
        pk(fmaf(-axl * q1.x, q1.x, fmaf(-ayl * q1.y, q1.y, LOG2_L2E)),
           fmaf(-axl * q1.z, q1.z, fmaf(-ayl * q1.w, q1.w, LOG2_L2E))));

    __syncthreads();

    float* op;
    if (n0 < NTR_) op = out + (b * NTR_ + n0) * T_ + 4 * tq;
    else           op = out + B_ * NTR_ * T_ + (b * NTE_ + (n0 - NTR_)) * T_ + 4 * tq;

    unsigned cbase = (unsigned)__cvta_generic_to_shared(sC);
    unsigned zxad  = (unsigned)__cvta_generic_to_shared(&sZ[0][tid]);
    unsigned zyad  = (unsigned)__cvta_generic_to_shared(&sZ[1][tid]);
    unsigned ltad  = (unsigned)__cvta_generic_to_shared(&sZ[2][tid]);

#pragma unroll
    for (int qi = 0; qi < NG; qi++) {
        const ulonglong2* pn = (const ulonglong2*)sN[qi];
        ulonglong2 A0 = pn[0], A1 = pn[1], A2 = pn[2], A3 = pn[3], A4 = pn[4];
        u64 pAp = A0.x, qAp = A0.y, EJp = A1.x, EW0p = A1.y;
        u64 Rxp = A2.x, Ryp = A2.y, Pxp = A3.x, Pyp = A3.y;
        u64 Lnp = A4.x, W1p = A4.y;

        float a0, a1;

        // lap inputs from smem (in-loop, register-free)
        u64 zx0, zx1, zy0, zy1, lt0, lt1;
        ldsV(zxad, zx0, zx1);
        ldsV(zyad, zy0, zy1);
        ldsV(ltad, lt0, lt1);

        // Euclidean leads (MUFU overlaps the FMA work below)
        u64 lap0 = f2fma(Pxp, zx0, f2fma(Pyp, zy0, f2add(Lnp, lt0)));
        u64 lap1 = f2fma(Pxp, zx1, f2fma(Pyp, zy1, f2add(Lnp, lt1)));
        upk(lap0, a0, a1);
        u64 lead0 = pk(ex2(a0), ex2(a1));
        upk(lap1, a0, a1);
        u64 lead1 = pk(ex2(a0), ex2(a1));

        u64 tx0 = f2mul(Rxp, Txp0), ty0 = f2mul(Ryp, Typ0);
        u64 tx1 = f2mul(Rxp, Txp1), ty1 = f2mul(Ryp, Typ1);

        // Torus (pure FMA): e0 = EW0 + v*(EW0 + EJ*v)
        u64 vv0 = f2fma(pAp, ssp0, f2mul(qAp, ccp0));
        u64 vv1 = f2fma(pAp, ssp1, f2mul(qAp, ccp1));
        u64 e0p0 = f2fma(vv0, f2fma(EJp, vv0, EW0p), EW0p);
        u64 e0p1 = f2fma(vv1, f2fma(EJp, vv1, EW0p), EW0p);

        // bicubic Horner: table loads shared across both pairs
        u64 c0r, c1r, c2r, c3r;
        ldsV(cbase +   0, c0r, c1r); ldsV(cbase +  16, c2r, c3r);
        u64 r0a = f2fma(f2fma(f2fma(c3r, tx0, c2r), tx0, c1r), tx0, c0r);
        u64 r0b = f2fma(f2fma(f2fma(c3r, tx1, c2r), tx1, c1r), tx1, c0r);
        ldsV(cbase +  32, c0r, c1r); ldsV(cbase +  48, c2r, c3r);
        u64 r1a = f2fma(f2fma(f2fma(c3r, tx0, c2r), tx0, c1r), tx0, c0r);
        u64 r1b = f2fma(f2fma(f2fma(c3r, tx1, c2r), tx1, c1r), tx1, c0r);
        ldsV(cbase +  64, c0r, c1r); ldsV(cbase +  80, c2r, c3r);
        u64 r2a = f2fma(f2fma(f2fma(c3r, tx0, c2r), tx0, c1r), tx0, c0r);
        u64 r2b = f2fma(f2fma(f2fma(c3r, tx1, c2r), tx1, c1r), tx1, c0r);
        ldsV(cbase +  96, c0r, c1r); ldsV(cbase + 112, c2r, c3r);
        u64 r3a = f2fma(f2fma(f2fma(c3r, tx0, c2r), tx0, c1r), tx0, c0r);
        u64 r3b = f2fma(f2fma(f2fma(c3r, tx1, c2r), tx1, c1r), tx1, c0r);

        u64 Sa = f2fma(f2fma(f2fma(r3a, ty0, r2a), ty0, r1a), ty0, r0a);
        u64 Sb = f2fma(f2fma(f2fma(r3b, ty1, r2b), ty1, r1b), ty1, r0b);

        // e1 = exp2(lead*S); out = e0 + W1*e1
        u64 g0 = f2mul(lead0, Sa);
        u64 g1 = f2mul(lead1, Sb);
        upk(g0, a0, a1);
        u64 e1p0 = pk(ex2(a0), ex2(a1));
        upk(g1, a0, a1);
        u64 e1p1 = pk(ex2(a0), ex2(a1));

        u64 o0 = f2fma(W1p, e1p0, e0p0);
        u64 o1 = f2fma(W1p, e1p1, e0p1);

        float4 v4;
        upk(o0, v4.x, v4.y);
        upk(o1, v4.z, v4.w);
        *reinterpret_cast<float4*>(op + qi * T_) = v4;   // STG.128, coalesced
    }
}

extern "C" void kernel_launch(void* const* d_in, const int* in_sizes, int n_in,
                              void* d_out, int out_size)
{
    const float* z0       = (const float*)d_in[0];
    const float* z1       = (const float*)d_in[1];
    const float* coeff0   = (const float*)d_in[2];
    const float* mean0    = (const float*)d_in[3];
    const float* log_var0 = (const float*)d_in[4];
    const float* coeff1   = (const float*)d_in[5];
    const float* mean1    = (const float*)d_in[6];
    const float* log_var1 = (const float*)d_in[7];
    const float* rf_tr0   = (const float*)d_in[8];
    const float* rf_tr1   = (const float*)d_in[9];
    const float* rf_te0   = (const float*)d_in[10];
    const float* rf_te1   = (const float*)d_in[11];
    const float* ew_tr    = (const float*)d_in[12];
    const float* ew_te    = (const float*)d_in[13];
    const float* lfs_tr   = (const float*)d_in[14];
    const float* lfs_te   = (const float*)d_in[15];

    decoder_fused<<<B_ * (NALL / NG), 64>>>(
        z0, z1, coeff0, mean0, log_var0, coeff1, mean1, log_var1,
        rf_tr0, rf_tr1, rf_te0, rf_te1, ew_tr, ew_te, lfs_tr, lfs_te,
        (float*)d_out);
}

// round 13
// speedup vs baseline: 1.1805x; 1.0201x over previous
#include <cuda_runtime.h>

#define B_   16
#define T_   256
#define NTR_ 1024
#define NTE_ 256
#define NALL 1280
#define NG   10           // n's per block; grid = 16 * 128 = 2048

#define L2E      1.4426950408889634f
#define LOG2_L2E 0.5287663729448977f

typedef unsigned long long u64;

__device__ __forceinline__ float ex2(float x) {
    float r; asm("ex2.approx.f32 %0, %1;" : "=f"(r) : "f"(x)); return r;
}
__device__ __forceinline__ u64 pk(float lo, float hi) {
    u64 r; asm("mov.b64 %0, {%1,%2};" : "=l"(r) : "f"(lo), "f"(hi)); return r;
}
__device__ __forceinline__ void upk(u64 v, float& lo, float& hi) {
    asm("mov.b64 {%0,%1}, %2;" : "=f"(lo), "=f"(hi) : "l"(v));
}
__device__ __forceinline__ u64 f2fma(u64 a, u64 b, u64 c) {
    u64 d; asm("fma.rn.f32x2 %0, %1, %2, %3;" : "=l"(d) : "l"(a), "l"(b), "l"(c)); return d;
}
__device__ __forceinline__ u64 f2mul(u64 a, u64 b) {
    u64 d; asm("mul.rn.f32x2 %0, %1, %2;" : "=l"(d) : "l"(a), "l"(b)); return d;
}
__device__ __forceinline__ u64 f2add(u64 a, u64 b) {
    u64 d; asm("add.rn.f32x2 %0, %1, %2;" : "=l"(d) : "l"(a), "l"(b)); return d;
}
// Volatile 128-bit shared load (broadcast address -> conflict-free, ~free on
// the crossbar): stays in-loop so the bicubic table never occupies
// long-lived registers.
__device__ __forceinline__ void ldsV(unsigned addr, u64& a, u64& b) {
    asm volatile("ld.shared.v2.u64 {%0,%1}, [%2];" : "=l"(a), "=l"(b) : "r"(addr));
}

// Block = (b, group of NG n's). 64 threads; thread tq owns the adjacent
// t-quad (4tq..4tq+3) as TWO packed f32x2 pairs, loops over NG n's.
// All per-thread state in registers (R12's smem offload regressed: per-thread
// LDS costs crossbar; broadcast LDS is free). NG=10 + 13 blocks/SM -> 1.06
// waves, prologue amortized over 10 n's.
__global__ void __launch_bounds__(64, 13)
decoder_fused(const float* __restrict__ z0,
              const float* __restrict__ z1,
              const float* __restrict__ coeff0,
              const float* __restrict__ mean0,
              const float* __restrict__ log_var0,
              const float* __restrict__ coeff1,
              const float* __restrict__ mean1,
              const float* __restrict__ log_var1,
              const float* __restrict__ rf_tr0,
              const float* __restrict__ rf_tr1,
              const float* __restrict__ rf_te0,
              const float* __restrict__ rf_te1,
              const float* __restrict__ ew_tr,
              const float* __restrict__ ew_te,
              const float* __restrict__ lfs_tr,
              const float* __restrict__ lfs_te,
              float* __restrict__ out)
{
    __shared__ float4 sN[NG][5];   // per-n consts, duplicated pairs
    __shared__ u64    sC[16];      // bicubic coeffs, duplicated pairs

    const int tid = threadIdx.x;
    const int bid = blockIdx.x;
    const int b   = bid / (NALL / NG);
    const int ng  = bid % (NALL / NG);
    const int n0  = ng * NG;

    // Global scalars every thread needs (broadcast loads, fast-math).
    const float dx  = mean1[8] - mean1[0];
    const float dy  = mean1[3] - mean1[1];
    const float ivx = __expf(-2.0f * log_var1[0]);  // 1/vx^2
    const float ivy = __expf(-2.0f * log_var1[1]);
    const float axl = ivx * L2E, ayl = ivy * L2E;
    const float kxl = 2.0f * dx * axl, kyl = 2.0f * dy * ayl;

    // ---- in-block per-n constant prep (fast-math intrinsics only) ----
    if (tid < NG) {
        int n = n0 + tid;
        int nn; const float *rf0, *rf1, *ew, *lfs;
        if (n < NTR_) { nn = n;        rf0 = rf_tr0; rf1 = rf_tr1; ew = ew_tr; lfs = lfs_tr; }
        else          { nn = n - NTR_; rf0 = rf_te0; rf1 = rf_te1; ew = ew_te; lfs = lfs_te; }

        // Torus: w0*e0 ~= EW0 + v*(EW0 + EJ*v), v = pA*s + qA*c (= A*w, |w|<=0.04)
        float mu  = mean0[0];
        float smu, cmu, sr, cr;
        __sincosf(mu, &smu, &cmu);
        __sincosf(rf0[nn], &sr, &cr);
        float ms  = smu - sr;
        float mc  = cmu - cr;
        float iv0 = __expf(-2.0f * log_var0[0]);
        float A   = coeff0[0] * __expf(-(1.0f + ms * ms + mc * mc) * iv0);
        float pA  = 2.0f * ms * iv0 * A;
        float qA  = 2.0f * mc * iv0 * A;

        float e0w = ew[nn * 2], e1w = ew[nn * 2 + 1];
        float mx  = fmaxf(e0w, e1w);
        float ea  = __expf(e0w - mx), eb = __expf(e1w - mx);
        float scl = __expf(lfs[nn]) / (ea + eb);
        float EW0 = ea * scl * __expf(A);               // w0 * exp(A)
        float EJ  = EW0 * (1.0f + A) / (2.0f * A);      // EW0 * J
        float W1  = eb * scl;

        float rx  = rf1[nn * 2 + 0] - mean1[0];
        float ry  = rf1[nn * 2 + 1] - mean1[1];
        float Rx  = ex2(kxl * rx), Ry = ex2(kyl * ry);
        float Px  = -2.0f * axl * rx, Py = -2.0f * ayl * ry;
        float Ln  = -axl * rx * rx - ayl * ry * ry;

        sN[tid][0] = make_float4(pA, pA, qA,  qA);
        sN[tid][1] = make_float4(EJ, EJ, EW0, EW0);
        sN[tid][2] = make_float4(Rx, Rx, Ry,  Ry);
        sN[tid][3] = make_float4(Px, Px, Py,  Py);
        sN[tid][4] = make_float4(Ln, Ln, W1,  W1);
    } else if (tid >= 32 && tid < 48) {
        int e = tid - 32;
        int i = e & 3, j = e >> 2;
        float v = coeff1[i * 4 + j] *
                  __expf(-(float)(i * i) * dx * dx * ivx - (float)(j * j) * dy * dy * ivy);
        sC[e] = pk(v, v);
    }

    // ---- per-thread t-quad prologue: two packed pairs (registers) ----
    const int tq = tid;
    float4 za = ((const float4*)z0)[b * (T_ / 4) + tq];          // z0[4tq..4tq+3]
    float4 q0 = ((const float4*)z1)[b * (T_ / 2) + 2 * tq];      // (zx0,zy0,zx1,zy1)
    float4 q1 = ((const float4*)z1)[b * (T_ / 2) + 2 * tq + 1];  // (zx2,zy2,zx3,zy3)

    float s0, c0, s1, c1, s2, c2, s3, c3;
    __sincosf(za.x, &s0, &c0);
    __sincosf(za.y, &s1, &c1);
    __sincosf(za.z, &s2, &c2);
    __sincosf(za.w, &s3, &c3);

    u64 ssp0 = pk(s0, s1), ccp0 = pk(c0, c1);
    u64 ssp1 = pk(s2, s3), ccp1 = pk(c2, c3);
    u64 Txp0 = pk(ex2(kxl * q0.x), ex2(kxl * q0.z));
    u64 Typ0 = pk(ex2(kyl * q0.y), ex2(kyl * q0.w));
    u64 Txp1 = pk(ex2(kxl * q1.x), ex2(kxl * q1.z));
    u64 Typ1 = pk(ex2(kyl * q1.y), ex2(kyl * q1.w));
    u64 Ltp0 = pk(fmaf(-axl * q0.x, q0.x, fmaf(-ayl * q0.y, q0.y, LOG2_L2E)),
                  fmaf(-axl * q0.z, q0.z, fmaf(-ayl * q0.w, q0.w, LOG2_L2E)));
    u64 Ltp1 = pk(fmaf(-axl * q1.x, q1.x, fmaf(-ayl * q1.y, q1.y, LOG2_L2E)),
                  fmaf(-axl * q1.z, q1.z, fmaf(-ayl * q1.w, q1.w, LOG2_L2E)));
    u64 zxp0 = pk(q0.x, q0.z), zyp0 = pk(q0.y, q0.w);
    u64 zxp1 = pk(q1.x, q1.z), zyp1 = pk(q1.y, q1.w);

    __syncthreads();

    // Output address: off(n) = n*T + (n < NTR ? cA : cB), in floats.
    const int cA = b * NTR_ * T_ + 4 * tq;
    const int cB = B_ * NTR_ * T_ + (b * NTE_ - NTR_) * T_ + 4 * tq;

    unsigned cbase = (unsigned)__cvta_generic_to_shared(sC);

#pragma unroll
    for (int qi = 0; qi < NG; qi++) {
        const ulonglong2* pn = (const ulonglong2*)sN[qi];
        ulonglong2 A0 = pn[0], A1 = pn[1], A2 = pn[2], A3 = pn[3], A4 = pn[4];
        u64 pAp = A0.x, qAp = A0.y, EJp = A1.x, EW0p = A1.y;
        u64 Rxp = A2.x, Ryp = A2.y, Pxp = A3.x, Pyp = A3.y;
        u64 Lnp = A4.x, W1p = A4.y;

        float a0, a1;

        // Euclidean leads (MUFU overlaps the FMA work below)
        u64 lap0 = f2fma(Pxp, zxp0, f2fma(Pyp, zyp0, f2add(Lnp, Ltp0)));
        u64 lap1 = f2fma(Pxp, zxp1, f2fma(Pyp, zyp1, f2add(Lnp, Ltp1)));
        upk(lap0, a0, a1);
        u64 lead0 = pk(ex2(a0), ex2(a1));
        upk(lap1, a0, a1);
        u64 lead1 = pk(ex2(a0), ex2(a1));

        u64 tx0 = f2mul(Rxp, Txp0), ty0 = f2mul(Ryp, Typ0);
        u64 tx1 = f2mul(Rxp, Txp1), ty1 = f2mul(Ryp, Typ1);

        // Torus (pure FMA): e0 = EW0 + v*(EW0 + EJ*v)
        u64 vv0 = f2fma(pAp, ssp0, f2mul(qAp, ccp0));
        u64 vv1 = f2fma(pAp, ssp1, f2mul(qAp, ccp1));
        u64 e0p0 = f2fma(vv0, f2fma(EJp, vv0, EW0p), EW0p);
        u64 e0p1 = f2fma(vv1, f2fma(EJp, vv1, EW0p), EW0p);

        // bicubic Horner: table loads (broadcast, ~free) shared across pairs
        u64 c0r, c1r, c2r, c3r;
        ldsV(cbase +   0, c0r, c1r); ldsV(cbase +  16, c2r, c3r);
        u64 r0a = f2fma(f2fma(f2fma(c3r, tx0, c2r), tx0, c1r), tx0, c0r);
        u64 r0b = f2fma(f2fma(f2fma(c3r, tx1, c2r), tx1, c1r), tx1, c0r);
        ldsV(cbase +  32, c0r, c1r); ldsV(cbase +  48, c2r, c3r);
        u64 r1a = f2fma(f2fma(f2fma(c3r, tx0, c2r), tx0, c1r), tx0, c0r);
        u64 r1b = f2fma(f2fma(f2fma(c3r, tx1, c2r), tx1, c1r), tx1, c0r);
        ldsV(cbase +  64, c0r, c1r); ldsV(cbase +  80, c2r, c3r);
        u64 r2a = f2fma(f2fma(f2fma(c3r, tx0, c2r), tx0, c1r), tx0, c0r);
        u64 r2b = f2fma(f2fma(f2fma(c3r, tx1, c2r), tx1, c1r), tx1, c0r);
        ldsV(cbase +  96, c0r, c1r); ldsV(cbase + 112, c2r, c3r);
        u64 r3a = f2fma(f2fma(f2fma(c3r, tx0, c2r), tx0, c1r), tx0, c0r);
        u64 r3b = f2fma(f2fma(f2fma(c3r, tx1, c2r), tx1, c1r), tx1, c0r);

        u64 Sa = f2fma(f2fma(f2fma(r3a, ty0, r2a), ty0, r1a), ty0, r0a);
        u64 Sb = f2fma(f2fma(f2fma(r3b, ty1, r2b), ty1, r1b), ty1, r0b);

        // e1 = exp2(lead*S); out = e0 + W1*e1
        u64 g0 = f2mul(lead0, Sa);
        u64 g1 = f2mul(lead1, Sb);
        upk(g0, a0, a1);
        u64 e1p0 = pk(ex2(a0), ex2(a1));
        upk(g1, a0, a1);
        u64 e1p1 = pk(ex2(a0), ex2(a1));

        u64 o0 = f2fma(W1p, e1p0, e0p0);
        u64 o1 = f2fma(W1p, e1p1, e0p1);

        float4 v4;
        upk(o0, v4.x, v4.y);
        upk(o1, v4.z, v4.w);

        int n   = n0 + qi;
        int off = n * T_ + (n < NTR_ ? cA : cB);
        *reinterpret_cast<float4*>(out + off) = v4;   // STG.128, coalesced
    }
}

extern "C" void kernel_launch(void* const* d_in, const int* in_sizes, int n_in,
                              void* d_out, int out_size)
{
    const float* z0       = (const float*)d_in[0];
    const float* z1       = (const float*)d_in[1];
    const float* coeff0   = (const float*)d_in[2];
    const float* mean0    = (const float*)d_in[3];
    const float* log_var0 = (const float*)d_in[4];
    const float* coeff1   = (const float*)d_in[5];
    const float* mean1    = (const float*)d_in[6];
    const float* log_var1 = (const float*)d_in[7];
    const float* rf_tr0   = (const float*)d_in[8];
    const float* rf_tr1   = (const float*)d_in[9];
    const float* rf_te0   = (const float*)d_in[10];
    const float* rf_te1   = (const float*)d_in[11];
    const float* ew_tr    = (const float*)d_in[12];
    const float* ew_te    = (const float*)d_in[13];
    const float* lfs_tr   = (const float*)d_in[14];
    const float* lfs_te   = (const float*)d_in[15];

    decoder_fused<<<B_ * (NALL / NG), 64>>>(
        z0, z1, coeff0, mean0, log_var0, coeff1, mean1, log_var1,
        rf_tr0, rf_tr1, rf_te0, rf_te1, ew_tr, ew_te, lfs_tr, lfs_te,
        (float*)d_out);
}